// round 3
// baseline (speedup 1.0000x reference)
#include <cuda_runtime.h>

// Sinkhorn OT loss. K = exp(-C/0.1) on 64x64 separates into 3-tap stencils
// per axis (|d|>=2 taps < 4.3e-18 relative -> below fp32 significance).
//   pool_kernel    : 512 CTAs, full-chip HBM, 8x8 sum-pool -> g_pooled
//   sinkhorn_kernel: 16 CTAs (1/batch) x 512 threads; 2 rows x 4 cols per
//                    thread in registers; horizontal via width-16 shuffles,
//                    vertical halos via double-buffered smem, 1 bar/half-step.
// Finalize folded in via last-CTA-arrives (deterministic sum order).

#define NBATCH 16
#define ITERS  50
#define EPS    1e-8f
#define W1     4.5399929762484854e-05f   // exp(-10) == 1^2*exp(-10*1^2)

__device__ float g_pooled[2][NBATCH][4096];
__device__ float g_costs[NBATCH];
__device__ int   g_done;

// ---------------------------------------------------------------- pooling
__global__ __launch_bounds__(256) void pool_kernel(const float* __restrict__ pred,
                                                   const float* __restrict__ gt) {
    const int bid    = blockIdx.x;          // 0..511
    const int tensor = bid >> 8;
    const int batch  = (bid >> 4) & 15;
    const int rb     = bid & 15;
    const float* src = (tensor ? gt : pred) + (size_t)batch * 262144;

    const int pr = rb * 4 + (threadIdx.x >> 6);
    const int pc = threadIdx.x & 63;
    const float4* p = (const float4*)(src + (size_t)pr * 4096 + pc * 8);

    float s = 0.f;
#pragma unroll
    for (int y = 0; y < 8; ++y) {
        float4 v0 = p[y * 128];
        float4 v1 = p[y * 128 + 1];
        s += (v0.x + v0.y) + (v0.z + v0.w) + (v1.x + v1.y) + (v1.z + v1.w);
    }
    g_pooled[tensor][batch][pr * 64 + pc] = s;
}

// ---------------------------------------------------------------- sinkhorn
__device__ __forceinline__ float blockReduceSum512(float val, float* red) {
#pragma unroll
    for (int o = 16; o; o >>= 1) val += __shfl_xor_sync(0xffffffffu, val, o);
    const int w = threadIdx.x >> 5, l = threadIdx.x & 31;
    __syncthreads();
    if (l == 0) red[w] = val;
    __syncthreads();
    float s = (((red[0] + red[1]) + (red[2] + red[3]))
             + ((red[4] + red[5]) + (red[6] + red[7])))
            + (((red[8] + red[9]) + (red[10] + red[11]))
             + ((red[12] + red[13]) + (red[14] + red[15])));
    __syncthreads();
    return s;
}

// thread owns rows {2*band, 2*band+1}, cols c0..c0+3 (seg = 16-lane group)
// out = tgt / (Ve(He(in)) + eps)
__device__ __forceinline__ void halfstep(
    float (&out)[2][4], const float (&tgt)[2][4], const float (&in)[2][4],
    int buf, int band, int c0, int seg,
    float (*htop)[34][64], float (*hbot)[34][64])
{
    float H[2][4];
#pragma unroll
    for (int i = 0; i < 2; ++i) {
        float lf = __shfl_up_sync(0xffffffffu, in[i][3], 1, 16);
        float rt = __shfl_down_sync(0xffffffffu, in[i][0], 1, 16);
        if (seg == 0)  lf = 0.f;
        if (seg == 15) rt = 0.f;
        H[i][0] = fmaf(W1, lf,       fmaf(W1, in[i][1], in[i][0]));
        H[i][1] = fmaf(W1, in[i][0], fmaf(W1, in[i][2], in[i][1]));
        H[i][2] = fmaf(W1, in[i][1], fmaf(W1, in[i][3], in[i][2]));
        H[i][3] = fmaf(W1, in[i][2], fmaf(W1, rt,       in[i][3]));
    }
    *(float4*)&htop[buf][band + 1][c0] = make_float4(H[0][0], H[0][1], H[0][2], H[0][3]);
    *(float4*)&hbot[buf][band + 1][c0] = make_float4(H[1][0], H[1][1], H[1][2], H[1][3]);
    __syncthreads();
    const float4 up = *(const float4*)&hbot[buf][band][c0];      // row 2b-1 (0-pad at band 0)
    const float4 dn = *(const float4*)&htop[buf][band + 2][c0];  // row 2b+2 (0-pad at band 31)
    const float upv[4] = {up.x, up.y, up.z, up.w};
    const float dnv[4] = {dn.x, dn.y, dn.z, dn.w};
#pragma unroll
    for (int j = 0; j < 4; ++j) {
        float s0 = fmaf(W1, upv[j],  fmaf(W1, H[1][j], H[0][j])) + EPS;
        float s1 = fmaf(W1, H[0][j], fmaf(W1, dnv[j],  H[1][j])) + EPS;
        out[0][j] = __fdividef(tgt[0][j], s0);
        out[1][j] = __fdividef(tgt[1][j], s1);
    }
}

__global__ __launch_bounds__(512, 1) void sinkhorn_kernel(float* __restrict__ out) {
    __shared__ float htop[2][34][64];
    __shared__ float hbot[2][34][64];
    __shared__ float red[16];

    const int t    = threadIdx.x;
    const int w    = t >> 5, l = t & 31;
    const int seg  = l & 15;
    const int band = 2 * w + (l >> 4);   // 0..31, 2 rows each
    const int c0   = seg * 4;
    const int bid  = blockIdx.x;

    // permanent zero pads: stores hit indices 1..32; loads hit hbot[0..31], htop[2..33]
    if (t < 64) {
        hbot[0][0][t]  = 0.f; hbot[1][0][t]  = 0.f;
        htop[0][33][t] = 0.f; htop[1][33][t] = 0.f;
    }

    float a[2][4], b[2][4], u[2][4], v[2][4];
    float asum = 0.f, bsum = 0.f;
    const float* pa = g_pooled[0][bid];
    const float* pb = g_pooled[1][bid];
#pragma unroll
    for (int i = 0; i < 2; ++i) {
        const float4 x = *(const float4*)(pa + (band * 2 + i) * 64 + c0);
        const float4 y = *(const float4*)(pb + (band * 2 + i) * 64 + c0);
        a[i][0] = x.x; a[i][1] = x.y; a[i][2] = x.z; a[i][3] = x.w;
        b[i][0] = y.x; b[i][1] = y.y; b[i][2] = y.z; b[i][3] = y.w;
        asum += (x.x + x.y) + (x.z + x.w);
        bsum += (y.x + y.y) + (y.z + y.w);
    }
    asum = blockReduceSum512(asum, red);
    bsum = blockReduceSum512(bsum, red);
    const float ra  = 1.f / fmaxf(asum, 1e-8f);
    const float rbv = 1.f / fmaxf(bsum, 1e-8f);
#pragma unroll
    for (int i = 0; i < 2; ++i)
#pragma unroll
        for (int j = 0; j < 4; ++j) {
            a[i][j] *= ra; b[i][j] *= rbv; u[i][j] = 1.f;
        }
    __syncthreads();   // pads + state visible

    for (int it = 0; it < ITERS; ++it) {
        halfstep(v, b, u, 0, band, c0, seg, htop, hbot);
        halfstep(u, a, v, 1, band, c0, seg, htop, hbot);
    }

    // cost = u . (M v);  Mv = Hg(v) + W1*(T[r-1]+T[r+1]),  T = v + 2*Hg(v)
    float HG[2][4], T[2][4];
#pragma unroll
    for (int i = 0; i < 2; ++i) {
        float lf = __shfl_up_sync(0xffffffffu, v[i][3], 1, 16);
        float rt = __shfl_down_sync(0xffffffffu, v[i][0], 1, 16);
        if (seg == 0)  lf = 0.f;
        if (seg == 15) rt = 0.f;
        HG[i][0] = W1 * (lf + v[i][1]);
        HG[i][1] = W1 * (v[i][0] + v[i][2]);
        HG[i][2] = W1 * (v[i][1] + v[i][3]);
        HG[i][3] = W1 * (v[i][2] + rt);
#pragma unroll
        for (int j = 0; j < 4; ++j) T[i][j] = fmaf(2.f, HG[i][j], v[i][j]);
    }
    *(float4*)&htop[0][band + 1][c0] = make_float4(T[0][0], T[0][1], T[0][2], T[0][3]);
    *(float4*)&hbot[0][band + 1][c0] = make_float4(T[1][0], T[1][1], T[1][2], T[1][3]);
    __syncthreads();
    const float4 up = *(const float4*)&hbot[0][band][c0];
    const float4 dn = *(const float4*)&htop[0][band + 2][c0];
    const float upv[4] = {up.x, up.y, up.z, up.w};
    const float dnv[4] = {dn.x, dn.y, dn.z, dn.w};

    float local = 0.f;
#pragma unroll
    for (int j = 0; j < 4; ++j) {
        const float mv0 = fmaf(W1, upv[j] + T[1][j], HG[0][j]);
        const float mv1 = fmaf(W1, T[0][j] + dnv[j], HG[1][j]);
        local = fmaf(u[0][j], mv0, fmaf(u[1][j], mv1, local));
    }
    const float cost = blockReduceSum512(local, red);

    if (t == 0) {
        const bool valid = (asum > 0.5f) && (bsum > 0.5f);
        g_costs[bid] = valid ? cost : 0.f;
        __threadfence();
        const int prev = atomicAdd(&g_done, 1);
        if (prev == NBATCH - 1) {
            g_done = 0;
            __threadfence();
            float s = 0.f;
#pragma unroll
            for (int i = 0; i < NBATCH; ++i) s += g_costs[i];
            out[0] = s * (1.f / (float)NBATCH);
        }
    }
}

extern "C" void kernel_launch(void* const* d_in, const int* in_sizes, int n_in,
                              void* d_out, int out_size) {
    (void)in_sizes; (void)n_in; (void)out_size;
    const float* pred = (const float*)d_in[0];
    const float* gt   = (const float*)d_in[1];
    pool_kernel<<<512, 256>>>(pred, gt);
    sinkhorn_kernel<<<NBATCH, 512>>>((float*)d_out);
}

// round 4
// speedup vs baseline: 1.2066x; 1.2066x over previous
#include <cuda_runtime.h>

// Sinkhorn OT loss on 64x64 pooled grids.
// K = exp(-C/0.1) = (I + W1*Dx)(I + W1*Dy) + (taps < 4.3e-18): W1 = exp(-10).
// W1^2 cross-term is ~8e-9 RELATIVE -> below fp32 eps. So K@x collapses to a
// single 5-point stencil: x + W1*(L+R+U+D). One smem halo exchange + ONE
// barrier per halfstep. 16 CTAs (1/batch) x 256 threads, 4x4 cells/thread.

#define NBATCH 16
#define ITERS  50
#define EPS    1e-8f
#define W1     4.5399929762484854e-05f   // exp(-10)

__device__ float g_pooled[2][NBATCH][4096];
__device__ float g_costs[NBATCH];
__device__ int   g_done;

// ---------------------------------------------------------------- pooling
__global__ __launch_bounds__(256) void pool_kernel(const float* __restrict__ pred,
                                                   const float* __restrict__ gt) {
    const int bid    = blockIdx.x;          // 0..511
    const int tensor = bid >> 8;
    const int batch  = (bid >> 4) & 15;
    const int rb     = bid & 15;
    const float* src = (tensor ? gt : pred) + (size_t)batch * 262144;

    const int pr = rb * 4 + (threadIdx.x >> 6);
    const int pc = threadIdx.x & 63;
    const float4* p = (const float4*)(src + (size_t)pr * 4096 + pc * 8);

    float s = 0.f;
#pragma unroll
    for (int y = 0; y < 8; ++y) {
        float4 v0 = p[y * 128];
        float4 v1 = p[y * 128 + 1];
        s += (v0.x + v0.y) + (v0.z + v0.w) + (v1.x + v1.y) + (v1.z + v1.w);
    }
    g_pooled[tensor][batch][pr * 64 + pc] = s;
}

// ---------------------------------------------------------------- sinkhorn
__device__ __forceinline__ float blockReduceSum256(float val, float* red) {
#pragma unroll
    for (int o = 16; o; o >>= 1) val += __shfl_xor_sync(0xffffffffu, val, o);
    const int w = threadIdx.x >> 5, l = threadIdx.x & 31;
    __syncthreads();
    if (l == 0) red[w] = val;
    __syncthreads();
    float s = ((red[0] + red[1]) + (red[2] + red[3]))
            + ((red[4] + red[5]) + (red[6] + red[7]));
    __syncthreads();
    return s;
}

// out = tgt / (in + W1*(L+R+U+D) + EPS)   -- single-phase 5-point halfstep.
// Thread owns rows 4*band..4*band+3, cols c0..c0+3. Halo rows (4b-1, 4b+4)
// come from BOT[rbuf][band] / TOP[rbuf][band+2] (prev halfstep's outputs);
// this halfstep stores its own boundary rows into wbuf. One barrier.
__device__ __forceinline__ void halfstep(
    float (&out)[4][4], const float (&tgt)[4][4], const float (&in)[4][4],
    int rbuf, int wbuf, int band, int c0, int seg,
    float (*TOP)[18][64], float (*BOT)[18][64])
{
    float lf[4], rt[4];
#pragma unroll
    for (int i = 0; i < 4; ++i) {
        lf[i] = __shfl_up_sync(0xffffffffu, in[i][3], 1, 16);
        rt[i] = __shfl_down_sync(0xffffffffu, in[i][0], 1, 16);
    }
    if (seg == 0)  { lf[0] = 0.f; lf[1] = 0.f; lf[2] = 0.f; lf[3] = 0.f; }
    if (seg == 15) { rt[0] = 0.f; rt[1] = 0.f; rt[2] = 0.f; rt[3] = 0.f; }

    const float4 u4 = *(const float4*)&BOT[rbuf][band][c0];       // grid row 4b-1
    const float4 d4 = *(const float4*)&TOP[rbuf][band + 2][c0];   // grid row 4b+4
    const float up[4] = {u4.x, u4.y, u4.z, u4.w};
    const float dn[4] = {d4.x, d4.y, d4.z, d4.w};

#pragma unroll
    for (int i = 0; i < 4; ++i) {
#pragma unroll
        for (int j = 0; j < 4; ++j) {
            const float L = (j == 0) ? lf[i] : in[i][j - 1];
            const float R = (j == 3) ? rt[i] : in[i][j + 1];
            const float U = (i == 0) ? up[j] : in[i - 1][j];
            const float D = (i == 3) ? dn[j] : in[i + 1][j];
            const float s = fmaf(W1, (L + R) + (U + D), in[i][j] + EPS);
            out[i][j] = __fdividef(tgt[i][j], s);
        }
    }
    *(float4*)&TOP[wbuf][band + 1][c0] = make_float4(out[0][0], out[0][1], out[0][2], out[0][3]);
    *(float4*)&BOT[wbuf][band + 1][c0] = make_float4(out[3][0], out[3][1], out[3][2], out[3][3]);
    __syncthreads();
}

__global__ __launch_bounds__(256, 1) void sinkhorn_kernel(float* __restrict__ out) {
    __shared__ float TOP[2][18][64];   // TOP[buf][band+1] = that band's row 4b
    __shared__ float BOT[2][18][64];   // BOT[buf][band+1] = that band's row 4b+3
    __shared__ float red[8];

    const int t    = threadIdx.x;
    const int w    = t >> 5, l = t & 31;
    const int seg  = l & 15;
    const int band = 2 * w + (l >> 4);   // 0..15
    const int c0   = seg * 4;
    const int bid  = blockIdx.x;

    // init halos: interior = 1 (u0 = 1), pads = 0
    for (int i = t; i < 2 * 18 * 64; i += 256) {
        ((float*)TOP)[i] = 1.f;
        ((float*)BOT)[i] = 1.f;
    }
    __syncthreads();
    if (t < 64) {
        TOP[0][17][t] = 0.f; TOP[1][17][t] = 0.f;   // below grid
        BOT[0][0][t]  = 0.f; BOT[1][0][t]  = 0.f;   // above grid
    }

    float a[4][4], b[4][4], u[4][4], v[4][4];
    float asum = 0.f, bsum = 0.f;
    const float* pa = g_pooled[0][bid];
    const float* pb = g_pooled[1][bid];
#pragma unroll
    for (int i = 0; i < 4; ++i) {
        const float4 x = *(const float4*)(pa + (band * 4 + i) * 64 + c0);
        const float4 y = *(const float4*)(pb + (band * 4 + i) * 64 + c0);
        a[i][0] = x.x; a[i][1] = x.y; a[i][2] = x.z; a[i][3] = x.w;
        b[i][0] = y.x; b[i][1] = y.y; b[i][2] = y.z; b[i][3] = y.w;
        asum += (x.x + x.y) + (x.z + x.w);
        bsum += (y.x + y.y) + (y.z + y.w);
    }
    asum = blockReduceSum256(asum, red);
    bsum = blockReduceSum256(bsum, red);
    const float ra  = 1.f / fmaxf(asum, 1e-8f);
    const float rbv = 1.f / fmaxf(bsum, 1e-8f);
#pragma unroll
    for (int i = 0; i < 4; ++i)
#pragma unroll
        for (int j = 0; j < 4; ++j) {
            a[i][j] *= ra; b[i][j] *= rbv; u[i][j] = 1.f;
        }
    __syncthreads();   // halo init + state visible

    // 50 iterations: v = b/(Ku+eps) [u-halos in buf0], u = a/(Kv+eps) [v-halos in buf1]
    for (int it = 0; it < ITERS; ++it) {
        halfstep(v, b, u, 0, 1, band, c0, seg, TOP, BOT);
        halfstep(u, a, v, 1, 0, band, c0, seg, TOP, BOT);
    }

    // cost = sum u .* (M v),  M v ~= W1 * (v_L + v_R + v_U + v_D)
    // v-halos still valid in buf1 (written halfstep 99, untouched since).
    float lf[4], rt[4];
#pragma unroll
    for (int i = 0; i < 4; ++i) {
        lf[i] = __shfl_up_sync(0xffffffffu, v[i][3], 1, 16);
        rt[i] = __shfl_down_sync(0xffffffffu, v[i][0], 1, 16);
    }
    if (seg == 0)  { lf[0] = 0.f; lf[1] = 0.f; lf[2] = 0.f; lf[3] = 0.f; }
    if (seg == 15) { rt[0] = 0.f; rt[1] = 0.f; rt[2] = 0.f; rt[3] = 0.f; }
    const float4 u4 = *(const float4*)&BOT[1][band][c0];
    const float4 d4 = *(const float4*)&TOP[1][band + 2][c0];
    const float up[4] = {u4.x, u4.y, u4.z, u4.w};
    const float dn[4] = {d4.x, d4.y, d4.z, d4.w};

    float local = 0.f;
#pragma unroll
    for (int i = 0; i < 4; ++i) {
#pragma unroll
        for (int j = 0; j < 4; ++j) {
            const float L = (j == 0) ? lf[i] : v[i][j - 1];
            const float R = (j == 3) ? rt[i] : v[i][j + 1];
            const float U = (i == 0) ? up[j] : v[i - 1][j];
            const float D = (i == 3) ? dn[j] : v[i + 1][j];
            local = fmaf(u[i][j], (L + R) + (U + D), local);
        }
    }
    const float cost = W1 * blockReduceSum256(local, red);

    if (t == 0) {
        const bool valid = (asum > 0.5f) && (bsum > 0.5f);
        g_costs[bid] = valid ? cost : 0.f;
        __threadfence();
        const int prev = atomicAdd(&g_done, 1);
        if (prev == NBATCH - 1) {
            g_done = 0;
            __threadfence();
            float s = 0.f;
#pragma unroll
            for (int i = 0; i < NBATCH; ++i) s += g_costs[i];
            out[0] = s * (1.f / (float)NBATCH);
        }
    }
}

extern "C" void kernel_launch(void* const* d_in, const int* in_sizes, int n_in,
                              void* d_out, int out_size) {
    (void)in_sizes; (void)n_in; (void)out_size;
    const float* pred = (const float*)d_in[0];
    const float* gt   = (const float*)d_in[1];
    pool_kernel<<<512, 256>>>(pred, gt);
    sinkhorn_kernel<<<NBATCH, 256>>>((float*)d_out);
}